// round 6
// baseline (speedup 1.0000x reference)
#include <cuda_runtime.h>
#include <math.h>

// ---------------- problem constants ----------------
#define T_STEPS 2048
#define BATCH   64
#define DHID    512
#define NPRE    1536          // 3*DHID (r | z | g pre-activations from x)
#define CHUNK   256           // time steps per GEMM+recurrence pair
#define NCHUNK  (T_STEPS / CHUNK)
#define GRID_G  128           // persistent CTAs (all resident, 1/SM)
#define REC_THREADS 256
#define REC_SMEM_FLOATS (512*32 + 512*16 + 512*16 + 4096 + 256 + 256)
#define REC_SMEM_BYTES  (REC_SMEM_FLOATS * 4)   // 149504 B

// ---------------- device scratch (allocation-free rule: __device__ globals) ---
// One chunk of x-preactivations: 256*64*1536 floats = 100.7 MB
__device__ float g_xpre[(size_t)CHUNK * BATCH * NPRE];
__device__ float g_h[2][BATCH * DHID];                    // ping-pong hidden state
__device__ float g_rh[BATCH * DHID];                      // r * h exchange buffer
__device__ unsigned g_bar_cnt;                            // zero-init
__device__ volatile unsigned g_bar_gen;                   // zero-init

// ---------------- grid-wide barrier (generation counter, survives relaunch) --
__device__ __forceinline__ void grid_sync() {
    __threadfence();
    __syncthreads();
    if (threadIdx.x == 0) {
        unsigned my = g_bar_gen;
        unsigned a = atomicAdd(&g_bar_cnt, 1u);
        if (a == GRID_G - 1) {
            g_bar_cnt = 0;
            __threadfence();
            g_bar_gen = my + 1;
        } else {
            while (g_bar_gen == my) { __nanosleep(32); }
        }
    }
    __syncthreads();
}

__device__ __forceinline__ float fast_sigmoid(float x) {
    return 1.0f / (1.0f + __expf(-x));
}
__device__ __forceinline__ float fast_tanh(float x) {
    return 2.0f / (1.0f + __expf(-2.0f * x)) - 1.0f;
}

// =============================================================================
// Kernel 0: zero h0
// =============================================================================
__global__ void init_h_kernel() {
    g_h[0][blockIdx.x * 256 + threadIdx.x] = 0.f;
}

// =============================================================================
// Kernel 1: one chunk of Xpre = [x@Wr_x^T+br | x@Wz_x^T+bz | x@Wg_x^T+bg]
// M = CHUNK*B = 16384, N = 1536, K = 512. 128x128x8 tiles, 256 thr, 8x8 micro.
// =============================================================================
__global__ void __launch_bounds__(256)
gemm_xpre_kernel(const float* __restrict__ X,          // chunk base
                 const float* __restrict__ Wr, const float* __restrict__ Wz,
                 const float* __restrict__ Wg,
                 const float* __restrict__ br, const float* __restrict__ bz,
                 const float* __restrict__ bg)
{
    __shared__ float As[2][8][128];
    __shared__ float Bs[2][8][128];

    const int tid = threadIdx.x;
    const int nt  = blockIdx.x;          // 0..11
    const int mt  = blockIdx.y;          // 0..127
    const int m0  = mt * 128;
    const int n0  = nt * 128;

    const float* W; const float* bias;
    if (n0 < 512)       { W = Wr; bias = br; }
    else if (n0 < 1024) { W = Wz; bias = bz; }
    else                { W = Wg; bias = bg; }
    const int nb0 = n0 & 511;

    const int lrow = tid >> 1;           // 0..127
    const int lk4  = (tid & 1) * 4;      // 0 or 4

    const float* Aptr = X + (size_t)(m0 + lrow) * 512 + lk4;
    const float* Bptr = W + (size_t)(nb0 + lrow) * 1024 + lk4;  // x cols [0,512)

    float4 pa = *(const float4*)Aptr;
    float4 pb = *(const float4*)Bptr;
    As[0][lk4+0][lrow] = pa.x; As[0][lk4+1][lrow] = pa.y;
    As[0][lk4+2][lrow] = pa.z; As[0][lk4+3][lrow] = pa.w;
    Bs[0][lk4+0][lrow] = pb.x; Bs[0][lk4+1][lrow] = pb.y;
    Bs[0][lk4+2][lrow] = pb.z; Bs[0][lk4+3][lrow] = pb.w;
    __syncthreads();

    float acc[8][8];
    #pragma unroll
    for (int i = 0; i < 8; ++i)
        #pragma unroll
        for (int j = 0; j < 8; ++j) acc[i][j] = 0.f;

    const int ty = tid >> 4;             // 0..15
    const int tx = tid & 15;             // 0..15

    int buf = 0;
    for (int kt = 0; kt < 64; ++kt) {
        if (kt < 63) {
            pa = *(const float4*)(Aptr + (kt + 1) * 8);
            pb = *(const float4*)(Bptr + (kt + 1) * 8);
        }
        #pragma unroll
        for (int kk = 0; kk < 8; ++kk) {
            float ar[8], bc[8];
            *(float4*)&ar[0] = *(const float4*)&As[buf][kk][ty * 4];
            *(float4*)&ar[4] = *(const float4*)&As[buf][kk][64 + ty * 4];
            *(float4*)&bc[0] = *(const float4*)&Bs[buf][kk][tx * 4];
            *(float4*)&bc[4] = *(const float4*)&Bs[buf][kk][64 + tx * 4];
            #pragma unroll
            for (int i = 0; i < 8; ++i)
                #pragma unroll
                for (int j = 0; j < 8; ++j)
                    acc[i][j] += ar[i] * bc[j];
        }
        if (kt < 63) {
            int nb = buf ^ 1;
            As[nb][lk4+0][lrow] = pa.x; As[nb][lk4+1][lrow] = pa.y;
            As[nb][lk4+2][lrow] = pa.z; As[nb][lk4+3][lrow] = pa.w;
            Bs[nb][lk4+0][lrow] = pb.x; Bs[nb][lk4+1][lrow] = pb.y;
            Bs[nb][lk4+2][lrow] = pb.z; Bs[nb][lk4+3][lrow] = pb.w;
        }
        __syncthreads();
        buf ^= 1;
    }

    float bv[8];
    #pragma unroll
    for (int j = 0; j < 8; ++j) {
        int cj = (j < 4) ? (tx * 4 + j) : (64 + tx * 4 + (j - 4));
        bv[j] = bias[nb0 + cj];
    }
    #pragma unroll
    for (int i = 0; i < 8; ++i) {
        int ri = (i < 4) ? (ty * 4 + i) : (64 + ty * 4 + (i - 4));
        float* crow = g_xpre + (size_t)(m0 + ri) * NPRE + n0;
        float4 v0 = make_float4(acc[i][0]+bv[0], acc[i][1]+bv[1],
                                acc[i][2]+bv[2], acc[i][3]+bv[3]);
        float4 v1 = make_float4(acc[i][4]+bv[4], acc[i][5]+bv[5],
                                acc[i][6]+bv[6], acc[i][7]+bv[7]);
        *(float4*)(crow + tx * 4)      = v0;
        *(float4*)(crow + 64 + tx * 4) = v1;
    }
}

// =============================================================================
// Kernel 2: persistent recurrence for one CHUNK of steps.
// CTA owns batches [b0,b0+16), cols [c0,c0+16). Weights resident in SMEM.
//   A: r,z pre-acts (16b x 32c, k-split 8)  -> sigmoid -> r*h to g_rh, z local
//   B: g pre-acts   (16b x 16c, k-split 16) -> tanh    -> h_new to g_h + out
// =============================================================================
#define FMA44(acc, h4, w4)                                                     \
    acc[0][0] += h4.x * w4.x; acc[0][1] += h4.x * w4.y;                        \
    acc[0][2] += h4.x * w4.z; acc[0][3] += h4.x * w4.w;                        \
    acc[1][0] += h4.y * w4.x; acc[1][1] += h4.y * w4.y;                        \
    acc[1][2] += h4.y * w4.z; acc[1][3] += h4.y * w4.w;                        \
    acc[2][0] += h4.z * w4.x; acc[2][1] += h4.z * w4.y;                        \
    acc[2][2] += h4.z * w4.z; acc[2][3] += h4.z * w4.w;                        \
    acc[3][0] += h4.w * w4.x; acc[3][1] += h4.w * w4.y;                        \
    acc[3][2] += h4.w * w4.z; acc[3][3] += h4.w * w4.w;

__global__ void __launch_bounds__(REC_THREADS, 1)
gru_rec_kernel(const float* __restrict__ Wr, const float* __restrict__ Wz,
               const float* __restrict__ Wg, float* __restrict__ out,
               int mode, int t0)
{
    extern __shared__ float sm[];
    float* wrz  = sm;                    // [512 k][32 c] (c<16: Wr_h, else Wz_h)
    float* wg   = wrz + 512 * 32;        // [512 k][16 c] Wg_h
    float* hv   = wg  + 512 * 16;        // [512 k][16 b] staged h / r*h
    float* part = hv  + 512 * 16;        // [4096] k-split partials
    float* zsm  = part + 4096;           // [16 b][16 c] z
    float* hjs  = zsm + 256;             // [16 b][16 c] h(prev) at owned cols

    const int tid = threadIdx.x;
    const int cta = blockIdx.x;
    const int c0  = (cta & 31) * 16;     // 32 col tiles
    const int b0  = (cta >> 5) * 16;     // 4 batch tiles

    // ---- preload recurrent weights (h-part cols of W: [512..1024)) ----
    for (int i = tid; i < 512 * 32; i += REC_THREADS) {
        int k = i >> 5, cc = i & 31;
        wrz[i] = (cc < 16) ? Wr[(size_t)(c0 + cc) * 1024 + 512 + k]
                           : Wz[(size_t)(c0 + cc - 16) * 1024 + 512 + k];
    }
    for (int i = tid; i < 512 * 16; i += REC_THREADS) {
        int k = i >> 4, cc = i & 15;
        wg[i] = Wg[(size_t)(c0 + cc) * 1024 + 512 + k];
    }
    __syncthreads();

    const float4* hv4  = (const float4*)hv;
    const float4* wrz4 = (const float4*)wrz;
    const float4* wg4  = (const float4*)wg;

    for (int lt = 0; lt < CHUNK; ++lt) {
        const int t   = t0 + lt;
        const int cur = lt & 1;          // CHUNK even -> parity consistent

        // ---- stage h[b0..b0+16) into hv[k][b] ----
        {
            const int bb = tid & 15, kq = tid >> 4;
            const float4* src = (const float4*)(g_h[cur] + (b0 + bb) * DHID + kq * 32);
            #pragma unroll
            for (int q = 0; q < 8; ++q) {
                float4 v = __ldcg(src + q);
                int k = kq * 32 + q * 4;
                hv[(k+0)*16 + bb] = v.x; hv[(k+1)*16 + bb] = v.y;
                hv[(k+2)*16 + bb] = v.z; hv[(k+3)*16 + bb] = v.w;
            }
        }
        __syncthreads();

        // ---- phase A: r (cols 0..15) and z (cols 16..31), k split in 8 ----
        {
            const int bg = tid & 3, cg = (tid >> 2) & 7, ks = tid >> 5;
            float acc[4][4] = {};
            const int kb = ks * 64;
            #pragma unroll 4
            for (int k = kb; k < kb + 64; ++k) {
                float4 h4 = hv4[k * 4 + bg];
                float4 w4 = wrz4[k * 8 + cg];
                FMA44(acc, h4, w4)
            }
            #pragma unroll
            for (int i = 0; i < 4; ++i)
                *(float4*)&part[ks * 512 + (bg * 4 + i) * 32 + cg * 4] =
                    make_float4(acc[i][0], acc[i][1], acc[i][2], acc[i][3]);
        }
        __syncthreads();

        // ---- reduce + sigmoid; emit r*h, stash z and h ----
        for (int o = tid; o < 512; o += REC_THREADS) {
            int bb = o >> 5, ci = o & 31;
            float s = 0.f;
            #pragma unroll
            for (int p = 0; p < 8; ++p) s += part[p * 512 + o];
            int b = b0 + bb;
            size_t xb = (size_t)(lt * 64 + b) * NPRE;
            if (ci < 16) {
                int j = c0 + ci;
                float r = fast_sigmoid(s + g_xpre[xb + j]);
                float hval = hv[j * 16 + bb];
                hjs[bb * 16 + ci] = hval;
                g_rh[b * DHID + j] = r * hval;
            } else {
                int j = c0 + ci - 16;
                zsm[bb * 16 + (ci - 16)] = fast_sigmoid(s + g_xpre[xb + 512 + j]);
            }
        }
        grid_sync();   // all r*h visible

        // ---- stage r*h into hv[k][b] ----
        {
            const int bb = tid & 15, kq = tid >> 4;
            const float4* src = (const float4*)(g_rh + (b0 + bb) * DHID + kq * 32);
            #pragma unroll
            for (int q = 0; q < 8; ++q) {
                float4 v = __ldcg(src + q);
                int k = kq * 32 + q * 4;
                hv[(k+0)*16 + bb] = v.x; hv[(k+1)*16 + bb] = v.y;
                hv[(k+2)*16 + bb] = v.z; hv[(k+3)*16 + bb] = v.w;
            }
        }
        __syncthreads();

        // ---- phase B: g (16 cols), k split in 16 ----
        {
            const int bg = tid & 3, cg = (tid >> 2) & 3, ks = tid >> 4;
            float acc[4][4] = {};
            const int kb = ks * 32;
            #pragma unroll 4
            for (int k = kb; k < kb + 32; ++k) {
                float4 h4 = hv4[k * 4 + bg];
                float4 w4 = wg4[k * 4 + cg];
                FMA44(acc, h4, w4)
            }
            #pragma unroll
            for (int i = 0; i < 4; ++i)
                *(float4*)&part[ks * 256 + (bg * 4 + i) * 16 + cg * 4] =
                    make_float4(acc[i][0], acc[i][1], acc[i][2], acc[i][3]);
        }
        __syncthreads();

        // ---- finalize: tanh, h_new = z*h + (1-z)*g, store ----
        {
            const int o = tid;           // 256 outputs (16b x 16c)
            const int bb = o >> 4, cc = o & 15;
            float s = 0.f;
            #pragma unroll
            for (int p = 0; p < 16; ++p) s += part[p * 256 + o];
            int b = b0 + bb, j = c0 + cc;
            float gv = fast_tanh(s + g_xpre[(size_t)(lt * 64 + b) * NPRE + 1024 + j]);
            float z = zsm[o];
            float hn = z * hjs[o] + (1.f - z) * gv;
            g_h[cur ^ 1][b * DHID + j] = hn;
            if (mode >= 1) out[(size_t)(t * 64 + b) * 512 + j] = hn;
            if (t == T_STEPS - 1) {
                if (mode == 2)
                    out[(size_t)T_STEPS * BATCH * DHID + (size_t)b * 512 + j] = hn;
                else if (mode == 0)
                    out[(size_t)b * 512 + j] = hn;
            }
        }
        grid_sync();   // h_new visible for next step
    }
}

// =============================================================================
extern "C" void kernel_launch(void* const* d_in, const int* in_sizes, int n_in,
                              void* d_out, int out_size) {
    const float* x  = (const float*)d_in[0];
    const float* Wr = (const float*)d_in[1];
    const float* br = (const float*)d_in[2];
    const float* Wz = (const float*)d_in[3];
    const float* bz = (const float*)d_in[4];
    const float* Wg = (const float*)d_in[5];
    const float* bg = (const float*)d_in[6];
    float* out = (float*)d_out;

    const long long TBH = (long long)T_STEPS * BATCH * DHID;   // 67,108,864
    int mode;
    if ((long long)out_size >= TBH + (long long)BATCH * DHID) mode = 2; // outs + h_final
    else if ((long long)out_size >= TBH)                      mode = 1; // outs only
    else                                                      mode = 0; // h_final only

    cudaFuncSetAttribute(gru_rec_kernel,
                         cudaFuncAttributeMaxDynamicSharedMemorySize,
                         REC_SMEM_BYTES);

    init_h_kernel<<<BATCH * DHID / 256, 256>>>();

    dim3 g1(12, CHUNK * BATCH / 128);    // 12 N-tiles x 128 M-tiles
    for (int c = 0; c < NCHUNK; ++c) {
        const float* xc = x + (size_t)c * CHUNK * BATCH * 512;
        gemm_xpre_kernel<<<g1, 256>>>(xc, Wr, Wz, Wg, br, bz, bg);
        gru_rec_kernel<<<GRID_G, REC_THREADS, REC_SMEM_BYTES>>>(
            Wr, Wz, Wg, out, mode, c * CHUNK);
    }
}

// round 7
// speedup vs baseline: 1.2573x; 1.2573x over previous
#include <cuda_runtime.h>
#include <math.h>

// ---------------- problem constants ----------------
#define T_STEPS 2048
#define BATCH   64
#define DHID    512
#define NPRE    1536          // 3*DHID (r | z | g pre-activations from x)
#define CHUNK   256           // time steps per GEMM+recurrence pair
#define NCHUNK  (T_STEPS / CHUNK)
#define GRID_G  128           // persistent CTAs (all resident, 1/SM)
#define REC_THREADS 256
// wr + wz + wg + hv (each 512x16) + part (16x256)
#define REC_SMEM_FLOATS (512*16*4 + 4096)
#define REC_SMEM_BYTES  (REC_SMEM_FLOATS * 4)   // 147456 B

// ---------------- device scratch (allocation-free rule: __device__ globals) ---
__device__ float g_xpre[(size_t)CHUNK * BATCH * NPRE];    // 100.7 MB
__device__ float g_h[2][BATCH * DHID];                    // ping-pong hidden state
__device__ float g_rh[BATCH * DHID];                      // r * h exchange buffer
__device__ unsigned g_cnt_rh, g_cnt_h, g_cnt_exit;        // zero-init
__device__ volatile unsigned g_gen_rh, g_gen_h;           // zero-init

// ---------------- split grid barrier: arrive (thread0) / wait (thread0+bar) --
__device__ __forceinline__ void bar_arrive(unsigned* cnt, volatile unsigned* gen) {
    // caller: __syncthreads() already done; thread 0 only
    __threadfence();                       // publish CTA's global writes
    unsigned a = atomicAdd(cnt, 1u);
    if (a == GRID_G - 1) {
        *cnt = 0;
        __threadfence();
        *gen = *gen + 1;                   // single writer at a time
    }
}
__device__ __forceinline__ void bar_wait(volatile unsigned* gen, unsigned target) {
    if (threadIdx.x == 0) {
        while (*gen < target) { }          // tight L2 poll, 1 poller per CTA
    }
    __syncthreads();
}

__device__ __forceinline__ float fast_sigmoid(float x) {
    return 1.0f / (1.0f + __expf(-x));
}
__device__ __forceinline__ float fast_tanh(float x) {
    return 2.0f / (1.0f + __expf(-2.0f * x)) - 1.0f;
}

// =============================================================================
// Kernel 0: zero h0
// =============================================================================
__global__ void init_h_kernel() {
    g_h[0][blockIdx.x * 256 + threadIdx.x] = 0.f;
}

// =============================================================================
// Kernel 1: one chunk of Xpre = [x@Wr_x^T+br | x@Wz_x^T+bz | x@Wg_x^T+bg]
// M = CHUNK*B = 16384, N = 1536, K = 512. 128x128x8 tiles, 256 thr, 8x8 micro.
// (unchanged from R5 — 545us/chunk, fma 59% SOL)
// =============================================================================
__global__ void __launch_bounds__(256)
gemm_xpre_kernel(const float* __restrict__ X,
                 const float* __restrict__ Wr, const float* __restrict__ Wz,
                 const float* __restrict__ Wg,
                 const float* __restrict__ br, const float* __restrict__ bz,
                 const float* __restrict__ bg)
{
    __shared__ float As[2][8][128];
    __shared__ float Bs[2][8][128];

    const int tid = threadIdx.x;
    const int nt  = blockIdx.x;          // 0..11
    const int mt  = blockIdx.y;          // 0..127
    const int m0  = mt * 128;
    const int n0  = nt * 128;

    const float* W; const float* bias;
    if (n0 < 512)       { W = Wr; bias = br; }
    else if (n0 < 1024) { W = Wz; bias = bz; }
    else                { W = Wg; bias = bg; }
    const int nb0 = n0 & 511;

    const int lrow = tid >> 1;           // 0..127
    const int lk4  = (tid & 1) * 4;      // 0 or 4

    const float* Aptr = X + (size_t)(m0 + lrow) * 512 + lk4;
    const float* Bptr = W + (size_t)(nb0 + lrow) * 1024 + lk4;

    float4 pa = *(const float4*)Aptr;
    float4 pb = *(const float4*)Bptr;
    As[0][lk4+0][lrow] = pa.x; As[0][lk4+1][lrow] = pa.y;
    As[0][lk4+2][lrow] = pa.z; As[0][lk4+3][lrow] = pa.w;
    Bs[0][lk4+0][lrow] = pb.x; Bs[0][lk4+1][lrow] = pb.y;
    Bs[0][lk4+2][lrow] = pb.z; Bs[0][lk4+3][lrow] = pb.w;
    __syncthreads();

    float acc[8][8];
    #pragma unroll
    for (int i = 0; i < 8; ++i)
        #pragma unroll
        for (int j = 0; j < 8; ++j) acc[i][j] = 0.f;

    const int ty = tid >> 4;
    const int tx = tid & 15;

    int buf = 0;
    for (int kt = 0; kt < 64; ++kt) {
        if (kt < 63) {
            pa = *(const float4*)(Aptr + (kt + 1) * 8);
            pb = *(const float4*)(Bptr + (kt + 1) * 8);
        }
        #pragma unroll
        for (int kk = 0; kk < 8; ++kk) {
            float ar[8], bc[8];
            *(float4*)&ar[0] = *(const float4*)&As[buf][kk][ty * 4];
            *(float4*)&ar[4] = *(const float4*)&As[buf][kk][64 + ty * 4];
            *(float4*)&bc[0] = *(const float4*)&Bs[buf][kk][tx * 4];
            *(float4*)&bc[4] = *(const float4*)&Bs[buf][kk][64 + tx * 4];
            #pragma unroll
            for (int i = 0; i < 8; ++i)
                #pragma unroll
                for (int j = 0; j < 8; ++j)
                    acc[i][j] += ar[i] * bc[j];
        }
        if (kt < 63) {
            int nb = buf ^ 1;
            As[nb][lk4+0][lrow] = pa.x; As[nb][lk4+1][lrow] = pa.y;
            As[nb][lk4+2][lrow] = pa.z; As[nb][lk4+3][lrow] = pa.w;
            Bs[nb][lk4+0][lrow] = pb.x; Bs[nb][lk4+1][lrow] = pb.y;
            Bs[nb][lk4+2][lrow] = pb.z; Bs[nb][lk4+3][lrow] = pb.w;
        }
        __syncthreads();
        buf ^= 1;
    }

    float bv[8];
    #pragma unroll
    for (int j = 0; j < 8; ++j) {
        int cj = (j < 4) ? (tx * 4 + j) : (64 + tx * 4 + (j - 4));
        bv[j] = bias[nb0 + cj];
    }
    #pragma unroll
    for (int i = 0; i < 8; ++i) {
        int ri = (i < 4) ? (ty * 4 + i) : (64 + ty * 4 + (i - 4));
        float* crow = g_xpre + (size_t)(m0 + ri) * NPRE + n0;
        float4 v0 = make_float4(acc[i][0]+bv[0], acc[i][1]+bv[1],
                                acc[i][2]+bv[2], acc[i][3]+bv[3]);
        float4 v1 = make_float4(acc[i][4]+bv[4], acc[i][5]+bv[5],
                                acc[i][6]+bv[6], acc[i][7]+bv[7]);
        *(float4*)(crow + tx * 4)      = v0;
        *(float4*)(crow + 64 + tx * 4) = v1;
    }
}

// =============================================================================
// Kernel 2: persistent recurrence, one CHUNK of steps.
// CTA owns batches [b0,b0+16) x cols [c0,c0+16). Weights in SMEM k-major.
// Per step: r dots -> store r*h -> ARRIVE -> z dots (fills barrier window)
//           -> WAIT -> stage r*h -> g dots -> h_new -> ARRIVE.
// 1 output/thread in registers; xpre prefetched at step top.
// =============================================================================
#define FMA44(acc, h4, w4)                                                     \
    acc[0][0] += h4.x * w4.x; acc[0][1] += h4.x * w4.y;                        \
    acc[0][2] += h4.x * w4.z; acc[0][3] += h4.x * w4.w;                        \
    acc[1][0] += h4.y * w4.x; acc[1][1] += h4.y * w4.y;                        \
    acc[1][2] += h4.y * w4.z; acc[1][3] += h4.y * w4.w;                        \
    acc[2][0] += h4.z * w4.x; acc[2][1] += h4.z * w4.y;                        \
    acc[2][2] += h4.z * w4.z; acc[2][3] += h4.z * w4.w;                        \
    acc[3][0] += h4.w * w4.x; acc[3][1] += h4.w * w4.y;                        \
    acc[3][2] += h4.w * w4.z; acc[3][3] += h4.w * w4.w;

// One gate's dot products: 16b x 16c, k-split 16, acc 4x4 per thread.
#define GATE_DOTS(Wsm4)                                                        \
    {                                                                          \
        const int bg = tid & 3, cg = (tid >> 2) & 3, ks = tid >> 4;            \
        float acc[4][4] = {};                                                  \
        const int kb = ks * 32;                                                \
        _Pragma("unroll 4")                                                    \
        for (int k = kb; k < kb + 32; ++k) {                                   \
            float4 h4 = hv4[k * 4 + bg];                                       \
            float4 w4 = Wsm4[k * 4 + cg];                                      \
            FMA44(acc, h4, w4)                                                 \
        }                                                                      \
        _Pragma("unroll")                                                      \
        for (int i = 0; i < 4; ++i)                                            \
            *(float4*)&part[ks * 256 + (bg * 4 + i) * 16 + cg * 4] =           \
                make_float4(acc[i][0], acc[i][1], acc[i][2], acc[i][3]);       \
    }

#define REDUCE16(dst)                                                          \
    {                                                                          \
        float s = 0.f;                                                         \
        _Pragma("unroll")                                                      \
        for (int p = 0; p < 16; ++p) s += part[p * 256 + tid];                 \
        dst = s;                                                               \
    }

__global__ void __launch_bounds__(REC_THREADS, 1)
gru_rec_kernel(const float* __restrict__ Wr, const float* __restrict__ Wz,
               const float* __restrict__ Wg, float* __restrict__ out,
               int mode, int t0)
{
    extern __shared__ float sm[];
    float* wr   = sm;                    // [512 k][16 c]
    float* wz   = wr + 512 * 16;         // [512 k][16 c]
    float* wg   = wz + 512 * 16;         // [512 k][16 c]
    float* hv   = wg + 512 * 16;         // [512 k][16 b] staged h / r*h
    float* part = hv + 512 * 16;         // [16][256] k-split partials

    const int tid = threadIdx.x;
    const int cta = blockIdx.x;
    const int c0  = (cta & 31) * 16;     // 32 col tiles
    const int b0  = (cta >> 5) * 16;     // 4 batch tiles

    // ---- preload recurrent weights (h-part cols of W: [512..1024)) ----
    for (int i = tid; i < 512 * 16; i += REC_THREADS) {
        int k = i >> 4, cc = i & 15;
        size_t off = (size_t)(c0 + cc) * 1024 + 512 + k;
        wr[i] = Wr[off];
        wz[i] = Wz[off];
        wg[i] = Wg[off];
    }
    __syncthreads();

    const float4* hv4 = (const float4*)hv;
    const float4* wr4 = (const float4*)wr;
    const float4* wz4 = (const float4*)wz;
    const float4* wg4 = (const float4*)wg;

    // per-thread output coords
    const int bb = tid >> 4, cc = tid & 15;
    const int b  = b0 + bb,  j  = c0 + cc;
    const int sb = tid & 15, kq = tid >> 4;   // staging coords

    for (int lt = 0; lt < CHUNK; ++lt) {
        const int t   = t0 + lt;
        const int cur = lt & 1;          // CHUNK even -> parity consistent

        // ---- prefetch x-preactivations (off critical path) ----
        const size_t xb = (size_t)(lt * 64 + b) * NPRE + j;
        float xr = __ldcg(&g_xpre[xb]);
        float xz = __ldcg(&g_xpre[xb + 512]);
        float xg = __ldcg(&g_xpre[xb + 1024]);

        // ---- wait for previous step's h_new (all CTAs) ----
        if (lt > 0) bar_wait(&g_gen_h, (unsigned)lt);

        // ---- stage h[b0..b0+16) into hv[k][b] ----
        {
            const float4* src = (const float4*)(g_h[cur] + (b0 + sb) * DHID + kq * 32);
            #pragma unroll
            for (int q = 0; q < 8; ++q) {
                float4 v = __ldcg(src + q);
                int k = kq * 32 + q * 4;
                hv[(k+0)*16 + sb] = v.x; hv[(k+1)*16 + sb] = v.y;
                hv[(k+2)*16 + sb] = v.z; hv[(k+3)*16 + sb] = v.w;
            }
        }
        __syncthreads();

        // ---- r gate: dots -> reduce -> store r*h ----
        GATE_DOTS(wr4)
        __syncthreads();
        float rsum; REDUCE16(rsum)
        float hval = hv[j * 16 + bb];                 // h_prev at owned (b,j)
        float rv   = fast_sigmoid(rsum + xr);
        g_rh[b * DHID + j] = rv * hval;
        __syncthreads();                              // rh stores + part reads done
        if (tid == 0) bar_arrive(&g_cnt_rh, &g_gen_rh);

        // ---- z gate (overlaps other CTAs finishing r) ----
        GATE_DOTS(wz4)
        __syncthreads();
        float zsum; REDUCE16(zsum)
        float zv = fast_sigmoid(zsum + xz);

        // ---- wait for all r*h, stage into hv ----
        bar_wait(&g_gen_rh, (unsigned)(lt + 1));      // includes __syncthreads
        {
            const float4* src = (const float4*)(g_rh + (b0 + sb) * DHID + kq * 32);
            #pragma unroll
            for (int q = 0; q < 8; ++q) {
                float4 v = __ldcg(src + q);
                int k = kq * 32 + q * 4;
                hv[(k+0)*16 + sb] = v.x; hv[(k+1)*16 + sb] = v.y;
                hv[(k+2)*16 + sb] = v.z; hv[(k+3)*16 + sb] = v.w;
            }
        }
        __syncthreads();

        // ---- g gate: dots -> reduce -> h_new ----
        GATE_DOTS(wg4)
        __syncthreads();
        float gsum; REDUCE16(gsum)
        float gv = fast_tanh(gsum + xg);
        float hn = zv * hval + (1.f - zv) * gv;
        g_h[cur ^ 1][b * DHID + j] = hn;
        if (mode >= 1) out[(size_t)(t * 64 + b) * 512 + j] = hn;
        if (t == T_STEPS - 1) {
            if (mode == 2)
                out[(size_t)T_STEPS * BATCH * DHID + (size_t)b * 512 + j] = hn;
            else if (mode == 0)
                out[(size_t)b * 512 + j] = hn;
        }
        __syncthreads();
        if (tid == 0) bar_arrive(&g_cnt_h, &g_gen_h);
    }

    // ---- exit barrier: last CTA resets generations for next launch/replay ----
    __syncthreads();
    if (tid == 0) {
        unsigned a = atomicAdd(&g_cnt_exit, 1u);
        if (a == GRID_G - 1) {
            g_cnt_exit = 0;
            g_gen_rh = 0;
            g_gen_h  = 0;
            __threadfence();
        }
    }
}

// =============================================================================
extern "C" void kernel_launch(void* const* d_in, const int* in_sizes, int n_in,
                              void* d_out, int out_size) {
    const float* x  = (const float*)d_in[0];
    const float* Wr = (const float*)d_in[1];
    const float* br = (const float*)d_in[2];
    const float* Wz = (const float*)d_in[3];
    const float* bz = (const float*)d_in[4];
    const float* Wg = (const float*)d_in[5];
    const float* bg = (const float*)d_in[6];
    float* out = (float*)d_out;

    const long long TBH = (long long)T_STEPS * BATCH * DHID;   // 67,108,864
    int mode;
    if ((long long)out_size >= TBH + (long long)BATCH * DHID) mode = 2; // outs + h_final
    else if ((long long)out_size >= TBH)                      mode = 1; // outs only
    else                                                      mode = 0; // h_final only

    cudaFuncSetAttribute(gru_rec_kernel,
                         cudaFuncAttributeMaxDynamicSharedMemorySize,
                         REC_SMEM_BYTES);

    init_h_kernel<<<BATCH * DHID / 256, 256>>>();

    dim3 g1(12, CHUNK * BATCH / 128);    // 12 N-tiles x 128 M-tiles
    for (int c = 0; c < NCHUNK; ++c) {
        const float* xc = x + (size_t)c * CHUNK * BATCH * 512;
        gemm_xpre_kernel<<<g1, 256>>>(xc, Wr, Wz, Wg, br, bz, bg);
        gru_rec_kernel<<<GRID_G, REC_THREADS, REC_SMEM_BYTES>>>(
            Wr, Wz, Wg, out, mode, c * CHUNK);
    }
}

// round 8
// speedup vs baseline: 1.4668x; 1.1666x over previous
#include <cuda_runtime.h>
#include <math.h>

// ---------------- problem constants ----------------
#define T_STEPS 2048
#define BATCH   64
#define DHID    512
#define NPRE    1536          // 3*DHID (r | z | g pre-activations from x)
#define CHUNK   256           // time steps per GEMM+recurrence pair
#define NCHUNK  (T_STEPS / CHUNK)
#define GRID_G  128           // persistent CTAs (all resident, 1/SM)
#define GROUPS  4             // batch-tile groups of 32 CTAs (batch-independent)
#define REC_THREADS 256
// wr + wz + wg + hv (each 512x16) + part (16x256)
#define REC_SMEM_FLOATS (512*16*4 + 4096)
#define REC_SMEM_BYTES  (REC_SMEM_FLOATS * 4)   // 147456 B

// ---------------- device scratch (allocation-free rule: __device__ globals) ---
__device__ float g_xpre[(size_t)CHUNK * BATCH * NPRE];    // 100.7 MB
__device__ float g_h_tr[2][DHID * BATCH];                 // ping-pong h, [j][b]
__device__ float g_rh_tr[DHID * BATCH];                   // r*h exchange, [j][b]
__device__ volatile unsigned g_flags[GRID_G];             // per-CTA epoch (zero-init)
__device__ unsigned g_cnt_exit[GROUPS];                   // zero-init

__device__ __forceinline__ float fast_sigmoid(float x) {
    return 1.0f / (1.0f + __expf(-x));
}
__device__ __forceinline__ float fast_tanh(float x) {
    return 2.0f / (1.0f + __expf(-2.0f * x)) - 1.0f;
}

// ---- flag barrier: arrive = plain volatile store (no atomics) ---------------
__device__ __forceinline__ void flag_arrive(int cta, unsigned val) {
    // caller: __syncthreads() already done; thread 0 only
    __threadfence();                 // publish this CTA's global writes
    g_flags[cta] = val;
}
// wait until all 32 peer flags in this group reach target (warp 0 polls)
__device__ __forceinline__ void flag_wait(int grp, unsigned target) {
    if (threadIdx.x < 32) {
        const int peer = grp * 32 + (int)threadIdx.x;
        for (;;) {
            unsigned v = g_flags[peer];
            if (__all_sync(0xffffffffu, v >= target)) break;
        }
    }
    __syncthreads();
}

// =============================================================================
// Kernel 0: zero h0
// =============================================================================
__global__ void init_h_kernel() {
    g_h_tr[0][blockIdx.x * 256 + threadIdx.x] = 0.f;
}

// =============================================================================
// Kernel 1: one chunk of Xpre = [x@Wr_x^T+br | x@Wz_x^T+bz | x@Wg_x^T+bg]
// M = CHUNK*B = 16384, N = 1536, K = 512. (unchanged — 588us/chunk, fma 59%)
// =============================================================================
__global__ void __launch_bounds__(256)
gemm_xpre_kernel(const float* __restrict__ X,
                 const float* __restrict__ Wr, const float* __restrict__ Wz,
                 const float* __restrict__ Wg,
                 const float* __restrict__ br, const float* __restrict__ bz,
                 const float* __restrict__ bg)
{
    __shared__ float As[2][8][128];
    __shared__ float Bs[2][8][128];

    const int tid = threadIdx.x;
    const int nt  = blockIdx.x;          // 0..11
    const int mt  = blockIdx.y;          // 0..127
    const int m0  = mt * 128;
    const int n0  = nt * 128;

    const float* W; const float* bias;
    if (n0 < 512)       { W = Wr; bias = br; }
    else if (n0 < 1024) { W = Wz; bias = bz; }
    else                { W = Wg; bias = bg; }
    const int nb0 = n0 & 511;

    const int lrow = tid >> 1;           // 0..127
    const int lk4  = (tid & 1) * 4;      // 0 or 4

    const float* Aptr = X + (size_t)(m0 + lrow) * 512 + lk4;
    const float* Bptr = W + (size_t)(nb0 + lrow) * 1024 + lk4;

    float4 pa = *(const float4*)Aptr;
    float4 pb = *(const float4*)Bptr;
    As[0][lk4+0][lrow] = pa.x; As[0][lk4+1][lrow] = pa.y;
    As[0][lk4+2][lrow] = pa.z; As[0][lk4+3][lrow] = pa.w;
    Bs[0][lk4+0][lrow] = pb.x; Bs[0][lk4+1][lrow] = pb.y;
    Bs[0][lk4+2][lrow] = pb.z; Bs[0][lk4+3][lrow] = pb.w;
    __syncthreads();

    float acc[8][8];
    #pragma unroll
    for (int i = 0; i < 8; ++i)
        #pragma unroll
        for (int j = 0; j < 8; ++j) acc[i][j] = 0.f;

    const int ty = tid >> 4;
    const int tx = tid & 15;

    int buf = 0;
    for (int kt = 0; kt < 64; ++kt) {
        if (kt < 63) {
            pa = *(const float4*)(Aptr + (kt + 1) * 8);
            pb = *(const float4*)(Bptr + (kt + 1) * 8);
        }
        #pragma unroll
        for (int kk = 0; kk < 8; ++kk) {
            float ar[8], bc[8];
            *(float4*)&ar[0] = *(const float4*)&As[buf][kk][ty * 4];
            *(float4*)&ar[4] = *(const float4*)&As[buf][kk][64 + ty * 4];
            *(float4*)&bc[0] = *(const float4*)&Bs[buf][kk][tx * 4];
            *(float4*)&bc[4] = *(const float4*)&Bs[buf][kk][64 + tx * 4];
            #pragma unroll
            for (int i = 0; i < 8; ++i)
                #pragma unroll
                for (int j = 0; j < 8; ++j)
                    acc[i][j] += ar[i] * bc[j];
        }
        if (kt < 63) {
            int nb = buf ^ 1;
            As[nb][lk4+0][lrow] = pa.x; As[nb][lk4+1][lrow] = pa.y;
            As[nb][lk4+2][lrow] = pa.z; As[nb][lk4+3][lrow] = pa.w;
            Bs[nb][lk4+0][lrow] = pb.x; Bs[nb][lk4+1][lrow] = pb.y;
            Bs[nb][lk4+2][lrow] = pb.z; Bs[nb][lk4+3][lrow] = pb.w;
        }
        __syncthreads();
        buf ^= 1;
    }

    float bv[8];
    #pragma unroll
    for (int j = 0; j < 8; ++j) {
        int cj = (j < 4) ? (tx * 4 + j) : (64 + tx * 4 + (j - 4));
        bv[j] = bias[nb0 + cj];
    }
    #pragma unroll
    for (int i = 0; i < 8; ++i) {
        int ri = (i < 4) ? (ty * 4 + i) : (64 + ty * 4 + (i - 4));
        float* crow = g_xpre + (size_t)(m0 + ri) * NPRE + n0;
        float4 v0 = make_float4(acc[i][0]+bv[0], acc[i][1]+bv[1],
                                acc[i][2]+bv[2], acc[i][3]+bv[3]);
        float4 v1 = make_float4(acc[i][4]+bv[4], acc[i][5]+bv[5],
                                acc[i][6]+bv[6], acc[i][7]+bv[7]);
        *(float4*)(crow + tx * 4)      = v0;
        *(float4*)(crow + 64 + tx * 4) = v1;
    }
}

// =============================================================================
// Kernel 2: persistent recurrence, one CHUNK of steps.
// CTA owns batches [b0,b0+16) x cols [c0,c0+16); group = 32 CTAs sharing b0.
// Exchange buffers are [j][b]-major -> float4 LDG + STS.128 staging.
// Flags encode epoch: rh arrive = 2*lt+1, h arrive = 2*lt+2.
// =============================================================================
#define FMA44(acc, h4, w4)                                                     \
    acc[0][0] += h4.x * w4.x; acc[0][1] += h4.x * w4.y;                        \
    acc[0][2] += h4.x * w4.z; acc[0][3] += h4.x * w4.w;                        \
    acc[1][0] += h4.y * w4.x; acc[1][1] += h4.y * w4.y;                        \
    acc[1][2] += h4.y * w4.z; acc[1][3] += h4.y * w4.w;                        \
    acc[2][0] += h4.z * w4.x; acc[2][1] += h4.z * w4.y;                        \
    acc[2][2] += h4.z * w4.z; acc[2][3] += h4.z * w4.w;                        \
    acc[3][0] += h4.w * w4.x; acc[3][1] += h4.w * w4.y;                        \
    acc[3][2] += h4.w * w4.z; acc[3][3] += h4.w * w4.w;

#define GATE_DOTS(Wsm4)                                                        \
    {                                                                          \
        const int bg = tid & 3, cg = (tid >> 2) & 3, ks = tid >> 4;            \
        float acc[4][4] = {};                                                  \
        const int kb = ks * 32;                                                \
        _Pragma("unroll 4")                                                    \
        for (int k = kb; k < kb + 32; ++k) {                                   \
            float4 h4 = hv4[k * 4 + bg];                                       \
            float4 w4 = Wsm4[k * 4 + cg];                                      \
            FMA44(acc, h4, w4)                                                 \
        }                                                                      \
        _Pragma("unroll")                                                      \
        for (int i = 0; i < 4; ++i)                                            \
            *(float4*)&part[ks * 256 + (bg * 4 + i) * 16 + cg * 4] =           \
                make_float4(acc[i][0], acc[i][1], acc[i][2], acc[i][3]);       \
    }

#define REDUCE16(dst)                                                          \
    {                                                                          \
        float s = 0.f;                                                         \
        _Pragma("unroll")                                                      \
        for (int p = 0; p < 16; ++p) s += part[p * 256 + tid];                 \
        dst = s;                                                               \
    }

// stage [j][b]-major global buffer into hv[k=j][16 b]: float4 both sides
#define STAGE_TR(SRC)                                                          \
    {                                                                          \
        _Pragma("unroll")                                                      \
        for (int q = 0; q < 8; ++q) {                                          \
            const int jrow = jj * 8 + q;                                       \
            float4 v = __ldcg((const float4*)(SRC + jrow * 64 + b0) + q4);     \
            *(float4*)&hv[jrow * 16 + q4 * 4] = v;                             \
        }                                                                      \
    }

__global__ void __launch_bounds__(REC_THREADS, 1)
gru_rec_kernel(const float* __restrict__ Wr, const float* __restrict__ Wz,
               const float* __restrict__ Wg, float* __restrict__ out,
               int mode, int t0)
{
    extern __shared__ float sm[];
    float* wr   = sm;                    // [512 k][16 c]
    float* wz   = wr + 512 * 16;         // [512 k][16 c]
    float* wg   = wz + 512 * 16;         // [512 k][16 c]
    float* hv   = wg + 512 * 16;         // [512 k][16 b] staged h / r*h
    float* part = hv + 512 * 16;         // [16][256] k-split partials

    const int tid = threadIdx.x;
    const int cta = blockIdx.x;
    const int grp = cta >> 5;            // batch-tile group (0..3)
    const int c0  = (cta & 31) * 16;     // 32 col tiles
    const int b0  = grp * 16;            // batch tile

    // ---- preload recurrent weights (h-part cols of W: [512..1024)) ----
    for (int i = tid; i < 512 * 16; i += REC_THREADS) {
        int k = i >> 4, cc = i & 15;
        size_t off = (size_t)(c0 + cc) * 1024 + 512 + k;
        wr[i] = Wr[off];
        wz[i] = Wz[off];
        wg[i] = Wg[off];
    }
    __syncthreads();

    const float4* hv4 = (const float4*)hv;
    const float4* wr4 = (const float4*)wr;
    const float4* wz4 = (const float4*)wz;
    const float4* wg4 = (const float4*)wg;

    // per-thread output coords
    const int bb = tid >> 4, cc = tid & 15;
    const int b  = b0 + bb,  j  = c0 + cc;
    // staging coords
    const int q4 = tid & 3, jj = tid >> 2;   // jj: 0..63, q4: b-quad

    for (int lt = 0; lt < CHUNK; ++lt) {
        const int t   = t0 + lt;
        const int cur = lt & 1;

        // ---- prefetch x-preactivations (off critical path) ----
        const size_t xb = (size_t)(lt * 64 + b) * NPRE + j;
        float xr = __ldcg(&g_xpre[xb]);
        float xz = __ldcg(&g_xpre[xb + 512]);
        float xg = __ldcg(&g_xpre[xb + 1024]);

        // ---- wait for previous step's h_new (own group only) ----
        if (lt > 0) flag_wait(grp, (unsigned)(2 * lt));

        // ---- stage h into hv[k][b] ----
        STAGE_TR(g_h_tr[cur])
        __syncthreads();

        // ---- r gate ----
        GATE_DOTS(wr4)
        __syncthreads();
        float rsum; REDUCE16(rsum)
        float hval = hv[j * 16 + bb];                 // h_prev at owned (b,j)
        float rv   = fast_sigmoid(rsum + xr);
        g_rh_tr[j * 64 + b] = rv * hval;
        __syncthreads();                              // rh stores + part reads done
        if (tid == 0) flag_arrive(cta, (unsigned)(2 * lt + 1));

        // ---- z gate (fills barrier window) ----
        GATE_DOTS(wz4)
        __syncthreads();
        float zsum; REDUCE16(zsum)
        float zv = fast_sigmoid(zsum + xz);

        // ---- wait for group's r*h, stage into hv ----
        flag_wait(grp, (unsigned)(2 * lt + 1));
        STAGE_TR(g_rh_tr)
        __syncthreads();

        // ---- g gate ----
        GATE_DOTS(wg4)
        __syncthreads();
        float gsum; REDUCE16(gsum)
        float gv = fast_tanh(gsum + xg);
        float hn = zv * hval + (1.f - zv) * gv;
        g_h_tr[cur ^ 1][j * 64 + b] = hn;
        if (mode >= 1) out[(size_t)(t * 64 + b) * 512 + j] = hn;
        if (t == T_STEPS - 1) {
            if (mode == 2)
                out[(size_t)T_STEPS * BATCH * DHID + (size_t)b * 512 + j] = hn;
            else if (mode == 0)
                out[(size_t)b * 512 + j] = hn;
        }
        __syncthreads();
        if (tid == 0) flag_arrive(cta, (unsigned)(2 * lt + 2));
    }

    // ---- exit: last CTA of each group resets the group's flags ----
    __syncthreads();
    if (tid == 0) {
        unsigned a = atomicAdd(&g_cnt_exit[grp], 1u);
        if (a == 31) {
            g_cnt_exit[grp] = 0;
            for (int i = 0; i < 32; ++i) g_flags[grp * 32 + i] = 0;
            __threadfence();
        }
    }
}

// =============================================================================
extern "C" void kernel_launch(void* const* d_in, const int* in_sizes, int n_in,
                              void* d_out, int out_size) {
    const float* x  = (const float*)d_in[0];
    const float* Wr = (const float*)d_in[1];
    const float* br = (const float*)d_in[2];
    const float* Wz = (const float*)d_in[3];
    const float* bz = (const float*)d_in[4];
    const float* Wg = (const float*)d_in[5];
    const float* bg = (const float*)d_in[6];
    float* out = (float*)d_out;

    const long long TBH = (long long)T_STEPS * BATCH * DHID;   // 67,108,864
    int mode;
    if ((long long)out_size >= TBH + (long long)BATCH * DHID) mode = 2; // outs + h_final
    else if ((long long)out_size >= TBH)                      mode = 1; // outs only
    else                                                      mode = 0; // h_final only

    cudaFuncSetAttribute(gru_rec_kernel,
                         cudaFuncAttributeMaxDynamicSharedMemorySize,
                         REC_SMEM_BYTES);

    init_h_kernel<<<DHID * BATCH / 256, 256>>>();

    dim3 g1(12, CHUNK * BATCH / 128);    // 12 N-tiles x 128 M-tiles
    for (int c = 0; c < NCHUNK; ++c) {
        const float* xc = x + (size_t)c * CHUNK * BATCH * 512;
        gemm_xpre_kernel<<<g1, 256>>>(xc, Wr, Wz, Wg, br, bz, bg);
        gru_rec_kernel<<<GRID_G, REC_THREADS, REC_SMEM_BYTES>>>(
            Wr, Wz, Wg, out, mode, c * CHUNK);
    }
}